// round 16
// baseline (speedup 1.0000x reference)
#include <cuda_runtime.h>
#include <math.h>

#define N_G   1024
#define SCALE 1.0f
#define DXC   (2.0f / 31.0f)
#define QCUT  60.0f                // dropped terms < e^-30 of dominant: negligible
#define GPB   16                   // gaussians per block (phase B)
#define SEGCAP 64                  // per-warp candidate segment (64 j per warp)
#define GRID_TOTAL 256
#define NTHR  512

__device__ float d_img[N_G * 75];  // (N, 3, 5, 5): c*25 + kx*5 + ky
__device__ unsigned g_arrive;      // zero-init; reset at end of every run
__device__ unsigned g_depart;

__device__ __forceinline__ float tanha(float x) {
    float y;
    asm("tanh.approx.f32 %0, %1;" : "=f"(y) : "f"(x));
    return y;
}

// ---- dynamic smem layout (float offsets), all regions 16B-aligned ----
#define OFF_SWC   0        // 3750 (+2)
#define OFF_SWE   3752     // 180
#define OFF_SWL   3932     // 6400
#define OFF_SBC   10332    // 50 (+2)
#define OFF_SBE   10384    // 30 (+2)
#define OFF_SBL   10416    // 80
#define OFF_SHW   10496    // 160
#define OFF_SHB   10656    // 2 (+2)
#define OFF_SPRM  10660    // 144
// activation region (written only AFTER the barrier)
#define OFF_IMGT  10804    // 1200
#define OFF_SHT   12004    // 1280
#define OFF_SH2T  13284    // 1280
#define OFF_PP    14564    // 6 x 1280 = 7680
#define OFF_HP    22244    // 128
#define SMEM_FLTS 22372    // 89488 B -> 2 blocks/SM (179KB<=227), cap 296>=256

// Phase-A scratch aliases into activation region (pre-barrier only)
#define PA_CA    10804     // 16 segs * 64 float4 = 4096 floats
#define PA_CB    14900     // 4096 floats
#define PA_SCNT  18996     // 16
#define PA_PUS   19012     // 300 (3 partials x 100)
#define PA_PPD   19312     // 300

__global__ void __launch_bounds__(NTHR) k_all(
    const float* __restrict__ means,  const float* __restrict__ u,
    const float* __restrict__ scaling,const float* __restrict__ transform,
    const float* __restrict__ conv_w, const float* __restrict__ conv_b,
    const float* __restrict__ emb_w,  const float* __restrict__ emb_b,
    const float* __restrict__ lin1_w, const float* __restrict__ lin1_b,
    const float* __restrict__ sol_w,  const float* __restrict__ sol_b,
    const float* __restrict__ tr_w,   const float* __restrict__ tr_b,
    const float* __restrict__ sc_w,   const float* __restrict__ sc_b,
    const float* __restrict__ tf_w,   const float* __restrict__ tf_b,
    float* __restrict__ out)
{
    extern __shared__ float sm[];
    const int b    = blockIdx.x;
    const int tid  = threadIdx.x;
    const int w    = tid >> 5;
    const int lane = tid & 31;

    const int m  = b & 3;               // network
    const int g0 = (b >> 2) * GPB;      // phase-B gaussian base
    const int od = (m == 1 || m == 2) ? 2 : 1;

    // ============ pre-barrier loads (overlap with phase A) ============
    {
        const float4* lw4 = (const float4*)(lin1_w + m * 6400);
        float4* sl4 = (float4*)(sm + OFF_SWL);
        for (int idx = tid; idx < 1600; idx += NTHR) sl4[idx] = lw4[idx];
        const float2* cw2 = (const float2*)(conv_w + m * 3750);
        float2* sc2 = (float2*)(sm + OFF_SWC);
        for (int idx = tid; idx < 1875; idx += NTHR) sc2[idx] = cw2[idx];
        const float2* ew2 = (const float2*)(emb_w + m * 180);
        float2* se2 = (float2*)(sm + OFF_SWE);
        if (tid < 90) se2[tid] = ew2[tid];
    }
    if (tid < 50) sm[OFF_SBC + tid] = conv_b[m * 50 + tid];
    if (tid >= 64 && tid < 94)  sm[OFF_SBE + tid - 64] = emb_b[m * 30 + (tid - 64)];
    if (tid >= 96 && tid < 176) sm[OFF_SBL + tid - 96] = lin1_b[m * 80 + (tid - 96)];
    {
        const float* hw; const float* hb;
        if      (m == 0) { hw = sol_w; hb = sol_b; }
        else if (m == 1) { hw = tr_w;  hb = tr_b;  }
        else if (m == 2) { hw = sc_w;  hb = sc_b;  }
        else             { hw = tf_w;  hb = tf_b;  }
        if (tid >= 192 && tid - 192 < 80 * od) sm[OFF_SHW + tid - 192] = hw[tid - 192];
        if (tid < od) sm[OFF_SHB + tid] = hb[tid];
    }
    if (tid >= 448 && tid < 448 + GPB) {
        int g = tid - 448, i = g0 + g;
        sm[OFF_SPRM + g * 9 + 0] = means[2 * i];
        sm[OFF_SPRM + g * 9 + 1] = means[2 * i + 1];
        sm[OFF_SPRM + g * 9 + 2] = u[i];
        sm[OFF_SPRM + g * 9 + 3] = scaling[2 * i];
        sm[OFF_SPRM + g * 9 + 4] = scaling[2 * i + 1];
        sm[OFF_SPRM + g * 9 + 5] = transform[i];
    }

    // =================== PHASE A: sampling for gaussians [4b, 4b+4) ==========
    {
        float4* cA = (float4*)(sm + PA_CA);
        float4* cB = (float4*)(sm + PA_CB);
        int* s_scnt = (int*)(sm + PA_SCNT);
        float* pus = sm + PA_PUS;
        float* ppd = sm + PA_PPD;

        const int i0 = b * 4;
        float bminx = 1e30f, bmaxx = -1e30f, bminy = 1e30f, bmaxy = -1e30f;
        #pragma unroll
        for (int g = 0; g < 4; ++g) {
            float mx = means[2 * (i0 + g)], my = means[2 * (i0 + g) + 1];
            bminx = fminf(bminx, mx); bmaxx = fmaxf(bmaxx, mx);
            bminy = fminf(bminy, my); bmaxy = fmaxf(bmaxy, my);
        }
        bminx -= 2.0f * DXC; bmaxx += 2.0f * DXC;
        bminy -= 2.0f * DXC; bmaxy += 2.0f * DXC;

        // per-warp segmented scan: warp w owns j in [64w, 64w+64); no barriers
        {
            int cnt_w = 0;
            #pragma unroll
            for (int c = 0; c < 2; ++c) {
                int j = w * 64 + c * 32 + lane;
                float mx = means[2 * j], my = means[2 * j + 1];
                float s0 = scaling[2 * j], s1 = scaling[2 * j + 1], t = transform[j];
                float A = s0 * s0, B = s0 * t, C = t * t + s1 * s1;
                float inv = 1.0f / (A * C - B * B);
                float ca =  C * inv, cb = -B * inv, cc = A * inv;
                float h = 0.5f * (A + C);
                float r = sqrtf(0.25f * (A - C) * (A - C) + B * B);
                float r2max = QCUT * (h + r);
                float ddx = fmaxf(fmaxf(bminx - mx, mx - bmaxx), 0.0f);
                float ddy = fmaxf(fmaxf(bminy - my, my - bmaxy), 0.0f);
                bool pred = (ddx * ddx + ddy * ddy) <= r2max;
                unsigned bm = __ballot_sync(0xffffffffu, pred);
                if (pred) {
                    int idx = cnt_w + __popc(bm & ((1u << lane) - 1u));
                    cA[w * SEGCAP + idx] = make_float4(mx, my, r2max, u[j]);
                    cB[w * SEGCAP + idx] = make_float4(ca, cb, cc, ca + cc);
                }
                cnt_w += __popc(bm);
            }
            if (lane == 0) s_scnt[w] = cnt_w;
        }
        __syncthreads();   // segments + counts ready

        // evaluate 100 samples on 400 threads (4/sample), in-loop d2 prune
        float us = 0.0f, pd = 0.0f;
        float sx = 0.0f, sy = 0.0f;
        int   sl = 0;
        if (tid < 400) {
            int quart = tid / 100;
            sl = tid - quart * 100;
            const int i  = i0 + sl / 25;
            const int k  = sl % 25;
            const int kx = k / 5, ky = k % 5;
            sx = means[2 * i]     + (float)(kx - 2) * DXC;
            sy = means[2 * i + 1] + (float)(ky - 2) * DXC;
            #pragma unroll 1
            for (int sgm = 0; sgm < 16; ++sgm) {
                const int cn = s_scnt[sgm];
                const int base = sgm * SEGCAP;
                for (int t2 = quart; t2 < cn; t2 += 4) {
                    float4 A = cA[base + t2];
                    float dx = sx - A.x;
                    float dy = sy - A.y;
                    float d2 = dx * dx + dy * dy;
                    if (d2 <= A.z) {
                        float4 Bv = cB[base + t2];
                        float Cd0 = Bv.x * dx + Bv.y * dy;
                        float Cd1 = Bv.y * dx + Bv.z * dy;
                        float q   = dx * Cd0 + dy * Cd1;
                        float wv  = __expf(-0.5f * q) * A.w;
                        us += wv;
                        pd += wv * (Cd0 * Cd0 + Cd1 * Cd1 - Bv.w);
                    }
                }
            }
            if (quart > 0) { pus[(quart - 1) * 100 + sl] = us; ppd[(quart - 1) * 100 + sl] = pd; }
        }
        __syncthreads();
        if (tid < 100) {
            us += pus[sl] + pus[100 + sl] + pus[200 + sl];
            pd += ppd[sl] + ppd[100 + sl] + ppd[200 + sl];
            const int i = i0 + sl / 25;
            const int k = sl % 25;
            float maskv = (fabsf(sx) < SCALE && fabsf(sy) < SCALE) ? 1.0f : 0.0f;
            d_img[i * 75 +  0 + k] = us;
            d_img[i * 75 + 25 + k] = pd;
            d_img[i * 75 + 50 + k] = maskv;
        }
    }

    // ============ GRID BARRIER: one-shot atomic arrive, LOAD-based spin ======
    __threadfence();
    __syncthreads();
    if (tid == 0) {
        atomicAdd(&g_arrive, 1u);
        volatile unsigned* p = &g_arrive;
        while (*p < GRID_TOTAL) { }
    }
    __syncthreads();

    // =================== PHASE B: the 4 networks, 512-thread split ===========
    float* swc  = sm + OFF_SWC;
    float* swe  = sm + OFF_SWE;
    float* swl  = sm + OFF_SWL;
    float* sbc  = sm + OFF_SBC;
    float* sbe  = sm + OFF_SBE;
    float* sbl  = sm + OFF_SBL;
    float* shw  = sm + OFF_SHW;
    float* shb  = sm + OFF_SHB;
    float* sprm = sm + OFF_SPRM;
    float* imgT = sm + OFF_IMGT;
    float* shT  = sm + OFF_SHT;
    float* sh2T = sm + OFF_SH2T;
    float* pp   = sm + OFF_PP;
    float* hpart= sm + OFF_HP;

    for (int idx = tid; idx < GPB * 75; idx += NTHR) {
        int g = idx / 75, kk = idx - g * 75;
        imgT[kk * 16 + g] = d_img[(g0 + g) * 75 + kk];
    }
    __syncthreads();

    // ---- stage 1: conv on 400 threads (1o x 2g) + emb on 400..511 ----
    if (tid < 400) {
        int o  = tid >> 3;              // 0..49
        int gb = (tid & 7) * 2;         // 0,2,..,14
        float b0 = sbc[o];
        float a0 = b0, a1 = b0;
        const float* wr = &swc[o * 75];
        #pragma unroll 5
        for (int kk = 0; kk < 75; ++kk) {
            float wv = wr[kk];
            float2 v = *(const float2*)&imgT[kk * 16 + gb];
            a0 = fmaf(wv, v.x, a0);
            a1 = fmaf(wv, v.y, a1);
        }
        shT[o * 16 + gb]     = tanha(a0);
        shT[o * 16 + gb + 1] = tanha(a1);
    } else {
        int et = tid - 400;             // 0..111
        for (int task = et; task < 240; task += 112) {
            int q  = task >> 3;         // 0..29
            int gb = (task & 7) * 2;
            float be = sbe[q];
            float a0 = be, a1 = be;
            #pragma unroll
            for (int p = 0; p < 6; ++p) {
                float wv = swe[p * 30 + q];
                a0 = fmaf(sprm[gb * 9 + p],       wv, a0);
                a1 = fmaf(sprm[(gb + 1) * 9 + p], wv, a1);
            }
            shT[(50 + q) * 16 + gb]     = tanha(a0);
            shT[(50 + q) * 16 + gb + 1] = tanha(a1);
        }
    }
    __syncthreads();

    // ---- stage 2: 80x80 as 4q x 4g tiles, 6-way p split (480 threads) ----
    {
        if (tid < 480) {
            int chunk = tid / 80;            // 0..5
            int r = tid - chunk * 80;        // 0..79
            int q0 = (r >> 2) * 4;           // 0..76
            int gb = (r & 3) * 4;            // 0,4,8,12
            int pst = chunk * 13 + ((chunk < 2) ? chunk : 2);
            int pen = pst + 13 + (chunk < 2 ? 1 : 0);
            float acc[4][4];
            #pragma unroll
            for (int a = 0; a < 4; ++a)
                #pragma unroll
                for (int bb = 0; bb < 4; ++bb) acc[a][bb] = 0.0f;
            for (int p = pst; p < pen; ++p) {
                float4 wv = *(const float4*)&swl[p * 80 + q0];
                float4 hv = *(const float4*)&shT[p * 16 + gb];
                acc[0][0] = fmaf(wv.x, hv.x, acc[0][0]); acc[0][1] = fmaf(wv.x, hv.y, acc[0][1]);
                acc[0][2] = fmaf(wv.x, hv.z, acc[0][2]); acc[0][3] = fmaf(wv.x, hv.w, acc[0][3]);
                acc[1][0] = fmaf(wv.y, hv.x, acc[1][0]); acc[1][1] = fmaf(wv.y, hv.y, acc[1][1]);
                acc[1][2] = fmaf(wv.y, hv.z, acc[1][2]); acc[1][3] = fmaf(wv.y, hv.w, acc[1][3]);
                acc[2][0] = fmaf(wv.z, hv.x, acc[2][0]); acc[2][1] = fmaf(wv.z, hv.y, acc[2][1]);
                acc[2][2] = fmaf(wv.z, hv.z, acc[2][2]); acc[2][3] = fmaf(wv.z, hv.w, acc[2][3]);
                acc[3][0] = fmaf(wv.w, hv.x, acc[3][0]); acc[3][1] = fmaf(wv.w, hv.y, acc[3][1]);
                acc[3][2] = fmaf(wv.w, hv.z, acc[3][2]); acc[3][3] = fmaf(wv.w, hv.w, acc[3][3]);
            }
            float* dst = pp + chunk * 1280;
            #pragma unroll
            for (int a = 0; a < 4; ++a)
                #pragma unroll
                for (int bb = 0; bb < 4; ++bb)
                    dst[(q0 + a) * 16 + gb + bb] = acc[a][bb];
        }
        __syncthreads();
        // reduce 6 partials + bias + tanh  (1280 values over 512 threads)
        for (int idx = tid; idx < 1280; idx += NTHR) {
            int q = idx >> 4;
            float v = sbl[q] + pp[idx] + pp[1280 + idx] + pp[2560 + idx]
                              + pp[3840 + idx] + pp[5120 + idx] + pp[6400 + idx];
            sh2T[idx] = tanha(v);
        }
    }
    __syncthreads();

    // ---- stage 3: head, parallel over 4 p-chunks of 20 ----
    if (tid < od * 64) {
        int g = tid & 15;
        int r = tid >> 4;
        int d = r % od;
        int chunk = r / od;             // 0..3
        int pbase = chunk * 20;
        float acc = 0.0f;
        #pragma unroll 5
        for (int p = 0; p < 20; ++p)
            acc = fmaf(sh2T[(pbase + p) * 16 + g], shw[(pbase + p) * od + d], acc);
        hpart[(chunk * od + d) * 16 + g] = acc;
    }
    __syncthreads();
    if (tid < od * 16) {
        int g = tid & 15;
        int d = tid >> 4;
        float acc = shb[d];
        #pragma unroll
        for (int c = 0; c < 4; ++c) acc += hpart[(c * od + d) * 16 + g];
        int i = g0 + g;
        if      (m == 0) out[i * 6 + 0]     = sprm[g * 9 + 2]     + acc;
        else if (m == 1) out[i * 6 + 1 + d] = sprm[g * 9 + d]     + acc;
        else if (m == 2) out[i * 6 + 3 + d] = sprm[g * 9 + 3 + d] * __expf(acc);
        else             out[i * 6 + 5]     = sprm[g * 9 + 5]     + acc;
    }

    // ---- barrier counter reset (last block out restores initial state) ----
    __syncthreads();
    if (tid == 0) {
        unsigned d = atomicAdd(&g_depart, 1u) + 1u;
        if (d == GRID_TOTAL) { g_arrive = 0u; g_depart = 0u; __threadfence(); }
    }
}

// ---------------------------------------------------------------------------
extern "C" void kernel_launch(void* const* d_in, const int* in_sizes, int n_in,
                              void* d_out, int out_size)
{
    const float* means     = (const float*)d_in[0];
    const float* u         = (const float*)d_in[1];
    const float* scaling   = (const float*)d_in[2];
    const float* transform = (const float*)d_in[3];
    const float* conv_w    = (const float*)d_in[4];
    const float* conv_b    = (const float*)d_in[5];
    const float* emb_w     = (const float*)d_in[6];
    const float* emb_b     = (const float*)d_in[7];
    const float* lin1_w    = (const float*)d_in[8];
    const float* lin1_b    = (const float*)d_in[9];
    const float* sol_w     = (const float*)d_in[10];
    const float* sol_b     = (const float*)d_in[11];
    const float* tr_w      = (const float*)d_in[12];
    const float* tr_b      = (const float*)d_in[13];
    const float* sc_w      = (const float*)d_in[14];
    const float* sc_b      = (const float*)d_in[15];
    const float* tf_w      = (const float*)d_in[16];
    const float* tf_b      = (const float*)d_in[17];
    float* out             = (float*)d_out;

    static int smem_set = 0;
    if (!smem_set) {
        cudaFuncSetAttribute(k_all, cudaFuncAttributeMaxDynamicSharedMemorySize,
                             SMEM_FLTS * (int)sizeof(float));
        smem_set = 1;
    }

    k_all<<<GRID_TOTAL, NTHR, SMEM_FLTS * sizeof(float)>>>(
        means, u, scaling, transform,
        conv_w, conv_b, emb_w, emb_b, lin1_w, lin1_b,
        sol_w, sol_b, tr_w, tr_b, sc_w, sc_b, tf_w, tf_b, out);
}